// round 16
// baseline (speedup 1.0000x reference)
#include <cuda_runtime.h>

#define KTOT   1000000
#define NCOLS  70400
#define SENT   -9999999.0f

typedef unsigned long long u64;

// All layer-3/4 params in ONE constant struct (single staging memcpy node).
// W1/W2 stay on the shared (LDS) port inside the kernel.
struct CParams {
    ulonglong2 W3[324];   // 36 rows x 9 ulonglong2 (k-packed pairs)
    float      b3[36];
    float      W4[36];
    float      b4;
    float      pad[3];
};
__constant__ CParams cP;
__device__   CParams gStage;

static __device__ __forceinline__ u64 pack2(float lo, float hi) {
    u64 r; asm("mov.b64 %0,{%1,%2};" : "=l"(r) : "f"(lo), "f"(hi)); return r;
}
static __device__ __forceinline__ void unpack2(u64 v, float& lo, float& hi) {
    asm("mov.b64 {%0,%1},%2;" : "=f"(lo), "=f"(hi) : "l"(v));
}
static __device__ __forceinline__ u64 fma2(u64 a, u64 b, u64 c) {
    u64 d; asm("fma.rn.f32x2 %0,%1,%2,%3;" : "=l"(d) : "l"(a), "l"(b), "l"(c)); return d;
}
static __device__ __forceinline__ float hadd(u64 v) {
    float lo, hi; unpack2(v, lo, hi);
    return lo + hi;
}
// float atomic max via sign-split integer atomics (no return -> REDG)
static __device__ __forceinline__ void atomicMaxF(float* a, float v) {
    if (v >= 0.0f) atomicMax((int*)a, __float_as_int(v));
    else           atomicMin((unsigned int*)a, __float_as_uint(v));
}

__global__ void init_pack_kernel(float* out, int n,
                                 const float* __restrict__ W3,
                                 const float* __restrict__ b3,
                                 const float* __restrict__ W4,
                                 const float* __restrict__ b4) {
    int i = blockIdx.x * blockDim.x + threadIdx.x;
    if (i < n) out[i] = (i < NCOLS) ? SENT : 1.0f;
    float* sw3 = reinterpret_cast<float*>(gStage.W3);
    if (i < 1296) sw3[i] = W3[i];
    else if (i < 1332) gStage.b3[i - 1296] = b3[i - 1296];
    else if (i < 1368) gStage.W4[i - 1332] = W4[i - 1332];
    else if (i == 1368) gStage.b4 = b4[0];
}

__global__ __launch_bounds__(128) void mlp_scatter_kernel(
    const float* __restrict__ x,        // (4, K) row-major
    const int* __restrict__ tix,        // (K, 2) int32, col index at [2k+1]
    const float* __restrict__ W1, const float* __restrict__ b1,
    const float* __restrict__ W2, const float* __restrict__ b2,
    float* __restrict__ out)
{
    __shared__ ulonglong2 sW1[18];
    __shared__ ulonglong2 sW2[144];
    __shared__ u64        sW2t[36];
    __shared__ u64 sb1[18], sb2[36];

    const int t = threadIdx.x;
    for (int i = t; i < 18;  i += 128) sW1[i] = ((const ulonglong2*)W1)[i];
    for (int i = t; i < 18;  i += 128) sb1[i] = pack2(b1[i], 0.0f);
    for (int i = t; i < 144; i += 128) {
        int row = i >> 2, q = i & 3;
        sW2[i] = make_ulonglong2(((const u64*)W2)[row * 9 + 2 * q],
                                 ((const u64*)W2)[row * 9 + 2 * q + 1]);
    }
    for (int i = t; i < 36;  i += 128) sW2t[i] = ((const u64*)W2)[i * 9 + 8];
    for (int i = t; i < 36;  i += 128) sb2[i] = pack2(b2[i], 0.0f);
    __syncthreads();

    // 6 columns per thread = 3 pairs (KTOT % 6 = 4 -> per-pair predication)
    const unsigned k0 = 6u * (blockIdx.x * 128u + (unsigned)t);
    if (k0 >= KTOT) return;

    bool ok1 = (k0 + 2) < KTOT;
    bool ok2 = (k0 + 4) < KTOT;

    // Per pair p: 4 u64 = (f01 even-col, f23 even-col, f01 odd-col, f23 odd-col)
    u64 xv[3][4];
    #pragma unroll
    for (int p = 0; p < 3; p++) {
        float2 q0 = make_float2(0.f, 0.f), q1 = q0, q2 = q0, q3 = q0;
        if (p == 0 || (p == 1 && ok1) || (p == 2 && ok2)) {
            const unsigned kp = k0 + 2u * p;
            q0 = *reinterpret_cast<const float2*>(x + 0 * (size_t)KTOT + kp);
            q1 = *reinterpret_cast<const float2*>(x + 1 * (size_t)KTOT + kp);
            q2 = *reinterpret_cast<const float2*>(x + 2 * (size_t)KTOT + kp);
            q3 = *reinterpret_cast<const float2*>(x + 3 * (size_t)KTOT + kp);
        }
        xv[p][0] = pack2(q0.x, q1.x);
        xv[p][1] = pack2(q2.x, q3.x);
        xv[p][2] = pack2(q0.y, q1.y);
        xv[p][3] = pack2(q2.y, q3.y);
    }

    // ---- Layer 1: 4 -> 18, all 3 pairs in one sweep (12 chains) ----
    u64 h1[3][2][9];
    #pragma unroll
    for (int j = 0; j < 18; j += 2) {
        float ho[2][3][2];
        #pragma unroll
        for (int s = 0; s < 2; s++) {
            const int jj = j + s;
            ulonglong2 w = sW1[jj];
            u64 bb = sb1[jj];
            #pragma unroll
            for (int p = 0; p < 3; p++) {
                u64 a0 = fma2(w.x, xv[p][0], bb);
                u64 a1 = fma2(w.x, xv[p][2], bb);
                a0 = fma2(w.y, xv[p][1], a0);
                a1 = fma2(w.y, xv[p][3], a1);
                ho[s][p][0] = fmaxf(hadd(a0), 0.0f);
                ho[s][p][1] = fmaxf(hadd(a1), 0.0f);
            }
        }
        #pragma unroll
        for (int p = 0; p < 3; p++) {
            h1[p][0][j / 2] = pack2(ho[0][p][0], ho[1][p][0]);
            h1[p][1][j / 2] = pack2(ho[0][p][1], ho[1][p][1]);
        }
    }

    // ---- Layer 2: 18 -> 36, all 3 pairs in one sweep (each LDS feeds 6
    // FFMA2 chains) ----
    u64 h2[3][2][18];
    #pragma unroll 2
    for (int j = 0; j < 36; j += 2) {
        float ho[2][3][2];
        #pragma unroll
        for (int s = 0; s < 2; s++) {
            const int jj = j + s;
            u64 bb = sb2[jj];
            u64 a[3][2];
            #pragma unroll
            for (int p = 0; p < 3; p++) { a[p][0] = bb; a[p][1] = bb; }
            #pragma unroll
            for (int q = 0; q < 4; q++) {
                ulonglong2 w = sW2[jj * 4 + q];
                #pragma unroll
                for (int p = 0; p < 3; p++) {
                    a[p][0] = fma2(w.x, h1[p][0][2 * q], a[p][0]);
                    a[p][1] = fma2(w.x, h1[p][1][2 * q], a[p][1]);
                    a[p][0] = fma2(w.y, h1[p][0][2 * q + 1], a[p][0]);
                    a[p][1] = fma2(w.y, h1[p][1][2 * q + 1], a[p][1]);
                }
            }
            u64 wt = sW2t[jj];
            #pragma unroll
            for (int p = 0; p < 3; p++) {
                a[p][0] = fma2(wt, h1[p][0][8], a[p][0]);
                a[p][1] = fma2(wt, h1[p][1][8], a[p][1]);
                ho[s][p][0] = fmaxf(hadd(a[p][0]), 0.0f);
                ho[s][p][1] = fmaxf(hadd(a[p][1]), 0.0f);
            }
        }
        #pragma unroll
        for (int p = 0; p < 3; p++) {
            h2[p][0][j / 2] = pack2(ho[0][p][0], ho[1][p][0]);
            h2[p][1][j / 2] = pack2(ho[0][p][1], ho[1][p][1]);
        }
    }

    // ---- Layers 3+4 fused (constant-port weights): 36 -> 36 -> 1 ----
    // One row per iteration; 6 accumulator chains. W3 read exactly once.
    float v[3][2];
    #pragma unroll
    for (int p = 0; p < 3; p++) { v[p][0] = cP.b4; v[p][1] = cP.b4; }
    #pragma unroll 2
    for (int j = 0; j < 36; j++) {
        u64 bb = pack2(cP.b3[j], 0.0f);
        u64 a[3][2];
        #pragma unroll
        for (int p = 0; p < 3; p++) { a[p][0] = bb; a[p][1] = bb; }
        #pragma unroll
        for (int q = 0; q < 9; q++) {
            ulonglong2 w = cP.W3[j * 9 + q];
            #pragma unroll
            for (int p = 0; p < 3; p++) {
                a[p][0] = fma2(w.x, h2[p][0][2 * q], a[p][0]);
                a[p][1] = fma2(w.x, h2[p][1][2 * q], a[p][1]);
                a[p][0] = fma2(w.y, h2[p][0][2 * q + 1], a[p][0]);
                a[p][1] = fma2(w.y, h2[p][1][2 * q + 1], a[p][1]);
            }
        }
        float w4 = cP.W4[j];
        #pragma unroll
        for (int p = 0; p < 3; p++) {
            v[p][0] = fmaf(w4, fmaxf(hadd(a[p][0]), 0.0f), v[p][0]);
            v[p][1] = fmaf(w4, fmaxf(hadd(a[p][1]), 0.0f), v[p][1]);
        }
    }

    // Scatter: per pair, one int4 covers both columns' (row,col) records.
    {
        const int4 p0 = *reinterpret_cast<const int4*>(tix + 2 * (size_t)k0);
        if ((unsigned)p0.y < NCOLS) atomicMaxF(out + p0.y, v[0][0]);
        if ((unsigned)p0.w < NCOLS) atomicMaxF(out + p0.w, v[0][1]);
    }
    if (ok1) {
        const int4 p1 = *reinterpret_cast<const int4*>(tix + 2 * (size_t)k0 + 4);
        if ((unsigned)p1.y < NCOLS) atomicMaxF(out + p1.y, v[1][0]);
        if ((unsigned)p1.w < NCOLS) atomicMaxF(out + p1.w, v[1][1]);
    }
    if (ok2) {
        const int4 p2 = *reinterpret_cast<const int4*>(tix + 2 * (size_t)k0 + 8);
        if ((unsigned)p2.y < NCOLS) atomicMaxF(out + p2.y, v[2][0]);
        if ((unsigned)p2.w < NCOLS) atomicMaxF(out + p2.w, v[2][1]);
    }
}

extern "C" void kernel_launch(void* const* d_in, const int* in_sizes, int n_in,
                              void* d_out, int out_size) {
    const float* x   = (const float*)d_in[0];
    const int*   tix = (const int*)d_in[1];
    const float* W1 = (const float*)d_in[2];
    const float* b1 = (const float*)d_in[3];
    const float* W2 = (const float*)d_in[4];
    const float* b2 = (const float*)d_in[5];
    const float* W3 = (const float*)d_in[6];
    const float* b3 = (const float*)d_in[7];
    const float* W4 = (const float*)d_in[8];
    const float* b4 = (const float*)d_in[9];
    float* out = (float*)d_out;

    // Node 1: init output + gather layer-3/4 params into device staging.
    int nInit = out_size > 1369 ? out_size : 1369;
    init_pack_kernel<<<(nInit + 255) / 256, 256>>>(out, out_size, W3, b3, W4, b4);

    // Node 2: ONE memcpy staging -> constant bank.
    void* stageAddr = nullptr;
    cudaGetSymbolAddress(&stageAddr, gStage);
    cudaMemcpyToSymbolAsync(cP, stageAddr, sizeof(CParams), 0,
                            cudaMemcpyDeviceToDevice);

    // Node 3: main kernel (6 columns per thread).
    const int nthreads = (KTOT + 5) / 6;
    mlp_scatter_kernel<<<(nthreads + 127) / 128, 128>>>(
        x, tix, W1, b1, W2, b2, out);
}

// round 17
// speedup vs baseline: 1.0939x; 1.0939x over previous
#include <cuda_runtime.h>

#define KTOT   1000000
#define NCOLS  70400
#define SENT   -9999999.0f

typedef unsigned long long u64;

// All layer-3/4 params in ONE constant struct (single staging memcpy node).
// W1/W2 stay on the shared (LDS) port inside the kernel.
struct CParams {
    ulonglong2 W3[324];   // 36 rows x 9 ulonglong2 (k-packed pairs)
    float      b3[36];
    float      W4[36];
    float      b4;
    float      pad[3];
};
__constant__ CParams cP;
__device__   CParams gStage;

static __device__ __forceinline__ u64 pack2(float lo, float hi) {
    u64 r; asm("mov.b64 %0,{%1,%2};" : "=l"(r) : "f"(lo), "f"(hi)); return r;
}
static __device__ __forceinline__ void unpack2(u64 v, float& lo, float& hi) {
    asm("mov.b64 {%0,%1},%2;" : "=f"(lo), "=f"(hi) : "l"(v));
}
static __device__ __forceinline__ u64 fma2(u64 a, u64 b, u64 c) {
    u64 d; asm("fma.rn.f32x2 %0,%1,%2,%3;" : "=l"(d) : "l"(a), "l"(b), "l"(c)); return d;
}
static __device__ __forceinline__ float hadd(u64 v) {
    float lo, hi; unpack2(v, lo, hi);
    return lo + hi;
}
// float atomic max via sign-split integer atomics (no return -> REDG)
static __device__ __forceinline__ void atomicMaxF(float* a, float v) {
    if (v >= 0.0f) atomicMax((int*)a, __float_as_int(v));
    else           atomicMin((unsigned int*)a, __float_as_uint(v));
}

__global__ void init_pack_kernel(float* out, int n,
                                 const float* __restrict__ W3,
                                 const float* __restrict__ b3,
                                 const float* __restrict__ W4,
                                 const float* __restrict__ b4) {
    int i = blockIdx.x * blockDim.x + threadIdx.x;
    if (i < n) out[i] = (i < NCOLS) ? SENT : 1.0f;
    float* sw3 = reinterpret_cast<float*>(gStage.W3);
    if (i < 1296) sw3[i] = W3[i];
    else if (i < 1332) gStage.b3[i - 1296] = b3[i - 1296];
    else if (i < 1368) gStage.W4[i - 1332] = W4[i - 1332];
    else if (i == 1368) gStage.b4 = b4[0];
}

__global__ __launch_bounds__(128) void mlp_scatter_kernel(
    const float* __restrict__ x,        // (4, K) row-major
    const int* __restrict__ tix,        // (K, 2) int32, col index at [2k+1]
    const float* __restrict__ W1, const float* __restrict__ b1,
    const float* __restrict__ W2, const float* __restrict__ b2,
    float* __restrict__ out)
{
    __shared__ ulonglong2 sW1[18];
    __shared__ ulonglong2 sW2[144];
    __shared__ u64        sW2t[36];
    __shared__ u64 sb1[18], sb2[36];

    const int t = threadIdx.x;
    for (int i = t; i < 18;  i += 128) sW1[i] = ((const ulonglong2*)W1)[i];
    for (int i = t; i < 18;  i += 128) sb1[i] = pack2(b1[i], 0.0f);
    for (int i = t; i < 144; i += 128) {
        int row = i >> 2, q = i & 3;
        sW2[i] = make_ulonglong2(((const u64*)W2)[row * 9 + 2 * q],
                                 ((const u64*)W2)[row * 9 + 2 * q + 1]);
    }
    for (int i = t; i < 36;  i += 128) sW2t[i] = ((const u64*)W2)[i * 9 + 8];
    for (int i = t; i < 36;  i += 128) sb2[i] = pack2(b2[i], 0.0f);
    __syncthreads();

    const unsigned k0 = 4u * (blockIdx.x * 128u + (unsigned)t);
    if (k0 >= KTOT) return;

    // 4 columns: pair A = cols k0,k0+1 ; pair B = cols k0+2,k0+3.
    float4 r0 = *reinterpret_cast<const float4*>(x + 0 * (size_t)KTOT + k0);
    float4 r1 = *reinterpret_cast<const float4*>(x + 1 * (size_t)KTOT + k0);
    float4 r2 = *reinterpret_cast<const float4*>(x + 2 * (size_t)KTOT + k0);
    float4 r3 = *reinterpret_cast<const float4*>(x + 3 * (size_t)KTOT + k0);
    u64 xA0 = pack2(r0.x, r1.x), xA1 = pack2(r2.x, r3.x);
    u64 xA2 = pack2(r0.y, r1.y), xA3 = pack2(r2.y, r3.y);
    u64 xB0 = pack2(r0.z, r1.z), xB1 = pack2(r2.z, r3.z);
    u64 xB2 = pack2(r0.w, r1.w), xB3 = pack2(r2.w, r3.w);

    // ---- Layer 1: 4 -> 18, BOTH pairs in one sweep ----
    u64 h1A[2][9], h1B[2][9];
    #pragma unroll
    for (int j = 0; j < 18; j += 2) {
        float hoA[2][2], hoB[2][2];
        #pragma unroll
        for (int s = 0; s < 2; s++) {
            const int jj = j + s;
            ulonglong2 w = sW1[jj];
            u64 bb = sb1[jj];
            u64 a0 = fma2(w.x, xA0, bb);
            u64 a1 = fma2(w.x, xA2, bb);
            u64 b0 = fma2(w.x, xB0, bb);
            u64 b1v = fma2(w.x, xB2, bb);
            a0 = fma2(w.y, xA1, a0);
            a1 = fma2(w.y, xA3, a1);
            b0 = fma2(w.y, xB1, b0);
            b1v = fma2(w.y, xB3, b1v);
            hoA[s][0] = fmaxf(hadd(a0), 0.0f);
            hoA[s][1] = fmaxf(hadd(a1), 0.0f);
            hoB[s][0] = fmaxf(hadd(b0), 0.0f);
            hoB[s][1] = fmaxf(hadd(b1v), 0.0f);
        }
        h1A[0][j / 2] = pack2(hoA[0][0], hoA[1][0]);
        h1A[1][j / 2] = pack2(hoA[0][1], hoA[1][1]);
        h1B[0][j / 2] = pack2(hoB[0][0], hoB[1][0]);
        h1B[1][j / 2] = pack2(hoB[0][1], hoB[1][1]);
    }

    // ---- Layer 2: 18 -> 36, BOTH pairs in one sweep ----
    u64 h2A[2][18], h2B[2][18];
    #pragma unroll 2
    for (int j = 0; j < 36; j += 2) {
        float hoA[2][2], hoB[2][2];
        #pragma unroll
        for (int s = 0; s < 2; s++) {
            const int jj = j + s;
            u64 bb = sb2[jj];
            u64 a0 = bb, a1 = bb, b0 = bb, b1v = bb;
            #pragma unroll
            for (int q = 0; q < 4; q++) {
                ulonglong2 w = sW2[jj * 4 + q];
                a0 = fma2(w.x, h1A[0][2 * q], a0);
                a1 = fma2(w.x, h1A[1][2 * q], a1);
                b0 = fma2(w.x, h1B[0][2 * q], b0);
                b1v = fma2(w.x, h1B[1][2 * q], b1v);
                a0 = fma2(w.y, h1A[0][2 * q + 1], a0);
                a1 = fma2(w.y, h1A[1][2 * q + 1], a1);
                b0 = fma2(w.y, h1B[0][2 * q + 1], b0);
                b1v = fma2(w.y, h1B[1][2 * q + 1], b1v);
            }
            u64 wt = sW2t[jj];
            a0 = fma2(wt, h1A[0][8], a0);
            a1 = fma2(wt, h1A[1][8], a1);
            b0 = fma2(wt, h1B[0][8], b0);
            b1v = fma2(wt, h1B[1][8], b1v);
            hoA[s][0] = fmaxf(hadd(a0), 0.0f);
            hoA[s][1] = fmaxf(hadd(a1), 0.0f);
            hoB[s][0] = fmaxf(hadd(b0), 0.0f);
            hoB[s][1] = fmaxf(hadd(b1v), 0.0f);
        }
        h2A[0][j / 2] = pack2(hoA[0][0], hoA[1][0]);
        h2A[1][j / 2] = pack2(hoA[0][1], hoA[1][1]);
        h2B[0][j / 2] = pack2(hoB[0][0], hoB[1][0]);
        h2B[1][j / 2] = pack2(hoB[0][1], hoB[1][1]);
    }

    // ---- Layers 3+4 fused (constant-port weights): 36 -> 36 -> 1 ----
    // TWO rows per iteration -> 8 independent accumulator chains
    // (2 rows x 4 columns); W3 still read exactly once per thread.
    float v0 = cP.b4, v1 = v0, v2 = v0, v3 = v0;
    #pragma unroll 2
    for (int j = 0; j < 36; j += 2) {
        u64 bbA = pack2(cP.b3[j], 0.0f);
        u64 bbB = pack2(cP.b3[j + 1], 0.0f);
        u64 rA0 = bbA, rA1 = bbA, rA2 = bbA, rA3 = bbA;   // row j
        u64 rB0 = bbB, rB1 = bbB, rB2 = bbB, rB3 = bbB;   // row j+1
        #pragma unroll
        for (int q = 0; q < 9; q++) {
            ulonglong2 wA = cP.W3[j * 9 + q];
            ulonglong2 wB = cP.W3[(j + 1) * 9 + q];
            rA0 = fma2(wA.x, h2A[0][2 * q], rA0);
            rA1 = fma2(wA.x, h2A[1][2 * q], rA1);
            rA2 = fma2(wA.x, h2B[0][2 * q], rA2);
            rA3 = fma2(wA.x, h2B[1][2 * q], rA3);
            rB0 = fma2(wB.x, h2A[0][2 * q], rB0);
            rB1 = fma2(wB.x, h2A[1][2 * q], rB1);
            rB2 = fma2(wB.x, h2B[0][2 * q], rB2);
            rB3 = fma2(wB.x, h2B[1][2 * q], rB3);
            rA0 = fma2(wA.y, h2A[0][2 * q + 1], rA0);
            rA1 = fma2(wA.y, h2A[1][2 * q + 1], rA1);
            rA2 = fma2(wA.y, h2B[0][2 * q + 1], rA2);
            rA3 = fma2(wA.y, h2B[1][2 * q + 1], rA3);
            rB0 = fma2(wB.y, h2A[0][2 * q + 1], rB0);
            rB1 = fma2(wB.y, h2A[1][2 * q + 1], rB1);
            rB2 = fma2(wB.y, h2B[0][2 * q + 1], rB2);
            rB3 = fma2(wB.y, h2B[1][2 * q + 1], rB3);
        }
        float w4A = cP.W4[j], w4B = cP.W4[j + 1];
        v0 = fmaf(w4A, fmaxf(hadd(rA0), 0.0f), v0);
        v1 = fmaf(w4A, fmaxf(hadd(rA1), 0.0f), v1);
        v2 = fmaf(w4A, fmaxf(hadd(rA2), 0.0f), v2);
        v3 = fmaf(w4A, fmaxf(hadd(rA3), 0.0f), v3);
        v0 = fmaf(w4B, fmaxf(hadd(rB0), 0.0f), v0);
        v1 = fmaf(w4B, fmaxf(hadd(rB1), 0.0f), v1);
        v2 = fmaf(w4B, fmaxf(hadd(rB2), 0.0f), v2);
        v3 = fmaf(w4B, fmaxf(hadd(rB3), 0.0f), v3);
    }

    // (K,2) int32 pairs: column index at odd positions
    const int4 p01 = *reinterpret_cast<const int4*>(tix + 2 * (size_t)k0);
    const int4 p23 = *reinterpret_cast<const int4*>(tix + 2 * (size_t)k0 + 4);
    if ((unsigned)p01.y < NCOLS) atomicMaxF(out + p01.y, v0);
    if ((unsigned)p01.w < NCOLS) atomicMaxF(out + p01.w, v1);
    if ((unsigned)p23.y < NCOLS) atomicMaxF(out + p23.y, v2);
    if ((unsigned)p23.w < NCOLS) atomicMaxF(out + p23.w, v3);
}

extern "C" void kernel_launch(void* const* d_in, const int* in_sizes, int n_in,
                              void* d_out, int out_size) {
    const float* x   = (const float*)d_in[0];
    const int*   tix = (const int*)d_in[1];
    const float* W1 = (const float*)d_in[2];
    const float* b1 = (const float*)d_in[3];
    const float* W2 = (const float*)d_in[4];
    const float* b2 = (const float*)d_in[5];
    const float* W3 = (const float*)d_in[6];
    const float* b3 = (const float*)d_in[7];
    const float* W4 = (const float*)d_in[8];
    const float* b4 = (const float*)d_in[9];
    float* out = (float*)d_out;

    // Node 1: init output + gather layer-3/4 params into device staging.
    int nInit = out_size > 1369 ? out_size : 1369;
    init_pack_kernel<<<(nInit + 255) / 256, 256>>>(out, out_size, W3, b3, W4, b4);

    // Node 2: ONE memcpy staging -> constant bank.
    void* stageAddr = nullptr;
    cudaGetSymbolAddress(&stageAddr, gStage);
    cudaMemcpyToSymbolAsync(cP, stageAddr, sizeof(CParams), 0,
                            cudaMemcpyDeviceToDevice);

    // Node 3: main kernel (4 columns per thread).
    const int nthreads = KTOT / 4;
    mlp_scatter_kernel<<<(nthreads + 127) / 128, 128>>>(
        x, tix, W1, b1, W2, b2, out);
}